// round 12
// baseline (speedup 1.0000x reference)
#include <cuda_runtime.h>
#include <cuda_bf16.h>
#include <cstdint>

#define B_   512
#define NC   225
#define CK   256
#define MH   225
#define VD   256
#define OUTC 512

// ---------------- helpers ----------------
__device__ __forceinline__ uint32_t smem_u32(const void* p) {
    uint32_t a;
    asm("{ .reg .u64 t; cvta.to.shared.u64 t, %1; cvt.u32.u64 %0, t; }" : "=r"(a) : "l"(p));
    return a;
}
__device__ __forceinline__ void ldm4(uint32_t* r, uint32_t addr) {
    asm volatile("ldmatrix.sync.aligned.m8n8.x4.shared.b16 {%0,%1,%2,%3}, [%4];"
                 : "=r"(r[0]), "=r"(r[1]), "=r"(r[2]), "=r"(r[3]) : "r"(addr));
}
__device__ __forceinline__ uint32_t rna(uint32_t u) {
    uint32_t r;
    asm("cvt.rna.tf32.f32 %0, %1;" : "=r"(r) : "f"(__uint_as_float(u)));
    return r;
}
__device__ __forceinline__ void rna4(uint32_t* r) {
    r[0] = rna(r[0]); r[1] = rna(r[1]); r[2] = rna(r[2]); r[3] = rna(r[3]);
}
__device__ __forceinline__ void mma1688(float* d, const uint32_t* a, uint32_t b0, uint32_t b1) {
    asm volatile("mma.sync.aligned.m16n8k8.row.col.f32.tf32.tf32.f32 "
                 "{%0,%1,%2,%3}, {%4,%5,%6,%7}, {%8,%9}, {%0,%1,%2,%3};"
                 : "+f"(d[0]), "+f"(d[1]), "+f"(d[2]), "+f"(d[3])
                 : "r"(a[0]), "r"(a[1]), "r"(a[2]), "r"(a[3]), "r"(b0), "r"(b1));
}
__device__ __forceinline__ void cpa4(uint32_t d, const float* s, int sz) {
    asm volatile("cp.async.ca.shared.global [%0], [%1], 4, %2;" :: "r"(d), "l"(s), "r"(sz));
}
__device__ __forceinline__ void cpa16(uint32_t d, const float* s, int sz) {
    asm volatile("cp.async.cg.shared.global [%0], [%1], 16, %2;" :: "r"(d), "l"(s), "r"(sz));
}
#define CP_COMMIT() asm volatile("cp.async.commit_group;" ::: "memory")
#define CP_WAIT2()  asm volatile("cp.async.wait_group 2;" ::: "memory")
#define CP_WAIT1()  asm volatile("cp.async.wait_group 1;" ::: "memory")
#define CP_WAIT0()  asm volatile("cp.async.wait_group 0;" ::: "memory")
__device__ __forceinline__ int iabs(int x) { return x < 0 ? -x : x; }

// ---- phase-1 smem: 4 buffers, per buffer A 64x80 | B 256x80 ----
#define BUFB   5120
#define BUFSZ  25600
// ---- phase-2 smem (reuses phase-1 buffer space after mainloop1) ----
#define PT_O   0              // p tile f32 [64m][260w] = 66560 B
#define B2_O   66560          // 2 x m_out chunk [16n][264w] = 16896 B each
// ---- persistent ----
#define PW_O   102400
#define RMX_O  102560
#define RS_O   103584
#define SM_F   104608

// ========================= fused GEMM1+softmax+GEMM2 =======================
__global__ __launch_bounds__(256, 2)
void k_fused(const float* __restrict__ q_in, const float* __restrict__ m_in,
             const float* __restrict__ m_out, const float* __restrict__ q_out,
             float* __restrict__ p_out, float* __restrict__ out)
{
    extern __shared__ char sm[];
    const uint32_t su = smem_u32(sm);
    const int tid = threadIdx.x, lane = tid & 31, w = tid >> 5;
    const int mw = w & 1, nh = w >> 1;
    const int b = blockIdx.y, m0 = blockIdx.x * 64;

    float* PWS = (float*)(sm + PW_O);
    float* RMX = (float*)(sm + RMX_O);
    float* RS  = (float*)(sm + RS_O);
    if (tid < 32) {
        float v = 0.0625f;               // fold 1/sqrt(256)
        for (int i = 0; i < tid; i++) v *= 0.92f;
        PWS[tid] = v;
    }

    const float* Aq = q_in + (size_t)b * CK * MH;    // [c][m]
    const float* Bm = m_in + (size_t)b * NC * CK;    // [n][c]
    const float* Bo = m_out + (size_t)b * NC * VD;   // [n][v]

    float acc[2][8][4];
    #pragma unroll
    for (int s = 0; s < 2; s++)
        #pragma unroll
        for (int j = 0; j < 8; j++)
            #pragma unroll
            for (int c = 0; c < 4; c++) acc[s][j][c] = 0.f;

    // ---- phase-1 ldmatrix addresses ----
    const int row_a = (lane & 7) + ((lane >> 3) & 1) * 8;
    const int koff_a = (lane >> 4) * 16;
    const int nloc_b = (lane & 7) + ((lane >> 4) & 1) * 8;
    const int koff_b = ((lane >> 3) & 1) * 16;
    uint32_t a_ad[2], b_ad[4];
    #pragma unroll
    for (int s = 0; s < 2; s++)
        a_ad[s] = su + (uint32_t)((mw * 32 + s * 16 + row_a) * 80 + koff_a);
    #pragma unroll
    for (int jp = 0; jp < 4; jp++)
        b_ad[jp] = su + BUFB + (uint32_t)((nh * 64 + jp * 16 + nloc_b) * 80 + koff_b);

    // phase-1 copy maps
    const int amm = tid & 63, acb = (tid >> 6) * 4;
    const int agm = m0 + amm;
    const int agmc = (agm < MH) ? agm : 0;
    const int asz = (agm < MH) ? 4 : 0;
    const int bnn = tid;
    const int bnnc = (bnn < NC) ? bnn : 0;
    const int bsz = (bnn < NC) ? 16 : 0;

    auto ISSUE1 = [&](int ch) {
        const int c0 = ch * 16;
        const uint32_t bo = su + (uint32_t)((ch & 3) * BUFSZ);
        #pragma unroll
        for (int t = 0; t < 4; t++)
            cpa4(bo + amm * 80 + (acb + t) * 4,
                 Aq + (size_t)(c0 + acb + t) * MH + agmc, asz);
        #pragma unroll
        for (int q = 0; q < 4; q++)
            cpa16(bo + BUFB + bnn * 80 + q * 16,
                  Bm + (size_t)bnnc * CK + c0 + q * 4, bsz);
        CP_COMMIT();
    };
    auto MMA1 = [&](uint32_t bo) {
        #pragma unroll
        for (int ks = 0; ks < 2; ks++) {
            uint32_t a0[4], a1[4];
            ldm4(a0, a_ad[0] + bo + ks * 32);
            ldm4(a1, a_ad[1] + bo + ks * 32);
            rna4(a0); rna4(a1);
            #pragma unroll
            for (int jp = 0; jp < 4; jp++) {
                uint32_t bf[4];
                ldm4(bf, b_ad[jp] + bo + ks * 32);
                rna4(bf);
                mma1688(acc[0][2*jp],   a0, bf[0], bf[1]);
                mma1688(acc[0][2*jp+1], a0, bf[2], bf[3]);
                mma1688(acc[1][2*jp],   a1, bf[0], bf[1]);
                mma1688(acc[1][2*jp+1], a1, bf[2], bf[3]);
            }
        }
    };

    ISSUE1(0); ISSUE1(1); ISSUE1(2);
    for (int ch = 0; ch < 16; ch++) {
        if (ch < 13) { CP_WAIT2(); } else { CP_WAIT0(); }
        __syncthreads();
        MMA1((uint32_t)((ch & 3) * BUFSZ));
        if (ch + 3 < 16) ISSUE1(ch + 3);
    }

    // ---------------- fused masked softmax over n ----------------
    const int l4 = lane & 3, lr = lane >> 2;
    int rl[2][2], xm[2][2], ym[2][2];
    #pragma unroll
    for (int s = 0; s < 2; s++)
        #pragma unroll
        for (int h = 0; h < 2; h++) {
            rl[s][h] = mw * 32 + s * 16 + lr + h * 8;
            int gm = m0 + rl[s][h];
            int gmc = (gm < MH) ? gm : MH - 1;
            xm[s][h] = gmc / 15; ym[s][h] = gmc - 15 * xm[s][h];
        }

    float mx[2][2] = {{-1e30f, -1e30f}, {-1e30f, -1e30f}};
    #pragma unroll
    for (int s = 0; s < 2; s++)
        #pragma unroll
        for (int j = 0; j < 8; j++)
            #pragma unroll
            for (int h = 0; h < 2; h++)
                #pragma unroll
                for (int c = 0; c < 2; c++) {
                    int n = nh * 64 + j * 8 + 2 * l4 + c;
                    int xn = n / 15, yn = n - 15 * xn;
                    float v = (n < NC)
                        ? acc[s][j][2*h+c] * PWS[iabs(xn - xm[s][h]) + iabs(yn - ym[s][h])]
                        : -1e30f;
                    acc[s][j][2*h+c] = v;
                    mx[s][h] = fmaxf(mx[s][h], v);
                }
    #pragma unroll
    for (int s = 0; s < 2; s++)
        #pragma unroll
        for (int h = 0; h < 2; h++) {
            mx[s][h] = fmaxf(mx[s][h], __shfl_xor_sync(~0u, mx[s][h], 1));
            mx[s][h] = fmaxf(mx[s][h], __shfl_xor_sync(~0u, mx[s][h], 2));
            if (l4 == 0) RMX[nh * 64 + rl[s][h]] = mx[s][h];
        }
    __syncthreads();
    #pragma unroll
    for (int s = 0; s < 2; s++)
        #pragma unroll
        for (int h = 0; h < 2; h++) {
            float m1 = fmaxf(RMX[rl[s][h]], RMX[64 + rl[s][h]]);
            float m2 = fmaxf(RMX[128 + rl[s][h]], RMX[192 + rl[s][h]]);
            mx[s][h] = fmaxf(m1, m2);
        }
    float sum[2][2] = {{0.f, 0.f}, {0.f, 0.f}};
    #pragma unroll
    for (int s = 0; s < 2; s++)
        #pragma unroll
        for (int j = 0; j < 8; j++)
            #pragma unroll
            for (int h = 0; h < 2; h++) {
                sum[s][h] += __expf(acc[s][j][2*h]   - mx[s][h]);
                sum[s][h] += __expf(acc[s][j][2*h+1] - mx[s][h]);
            }
    __syncthreads();
    #pragma unroll
    for (int s = 0; s < 2; s++)
        #pragma unroll
        for (int h = 0; h < 2; h++) {
            sum[s][h] += __shfl_xor_sync(~0u, sum[s][h], 1);
            sum[s][h] += __shfl_xor_sync(~0u, sum[s][h], 2);
            if (l4 == 0) RS[nh * 64 + rl[s][h]] = sum[s][h];
        }
    __syncthreads();
    float inv[2][2];
    #pragma unroll
    for (int s = 0; s < 2; s++)
        #pragma unroll
        for (int h = 0; h < 2; h++)
            inv[s][h] = 1.0f / (RS[rl[s][h]] + RS[64 + rl[s][h]]
                              + RS[128 + rl[s][h]] + RS[192 + rl[s][h]]);

    // emit p (global output) + p tile into smem (pitch 260 words, zero-padded)
    float* pbase = p_out + (size_t)b * NC * MH;
    float* PT = (float*)(sm + PT_O);
    #pragma unroll
    for (int s = 0; s < 2; s++)
        #pragma unroll
        for (int h = 0; h < 2; h++) {
            int gm = m0 + rl[s][h];
            float* prow = PT + rl[s][h] * 260;
            #pragma unroll
            for (int j = 0; j < 8; j++) {
                int n0 = nh * 64 + j * 8 + 2 * l4;
                float p0 = __expf(acc[s][j][2*h]   - mx[s][h]) * inv[s][h];
                float p1 = __expf(acc[s][j][2*h+1] - mx[s][h]) * inv[s][h];
                float z0 = (n0 < NC) ? p0 : 0.0f;
                float z1 = (n0 + 1 < NC) ? p1 : 0.0f;
                *(float2*)(prow + n0) = make_float2(z0, z1);
                if (gm < MH) {
                    if (n0 < NC)     pbase[(size_t)n0 * MH + gm] = p0;
                    if (n0 + 1 < NC) pbase[(size_t)(n0 + 1) * MH + gm] = p1;
                }
            }
        }

    // =================== phase 2: D[m,v] = p * m_out ===================
    const int bnl = tid >> 4, bvq = tid & 15;    // B chunk copy map
    auto ISSUE2 = [&](int ch) {
        const int n0 = ch * 16;
        const uint32_t bo = su + (uint32_t)(B2_O + (ch & 1) * 16896);
        const int sz = (n0 + bnl < NC) ? 16 : 0;
        const float* brow = Bo + (size_t)((n0 + bnl < NC) ? (n0 + bnl) : 0) * VD + bvq * 16;
        #pragma unroll
        for (int i = 0; i < 4; i++)
            cpa16(bo + bnl * 1056 + bvq * 64 + i * 16, brow + i * 4, sz);
        CP_COMMIT();
    };
    const int gr = lane >> 2, ctg = lane & 3;
    auto MMA2 = [&](int ch) {
        const int n0 = ch * 16;
        const uint32_t* At = (const uint32_t*)(sm + PT_O);                       // [64][260]
        const uint32_t* Vt = (const uint32_t*)(sm + B2_O + (ch & 1) * 16896);    // [16][264]
        #pragma unroll
        for (int ks = 0; ks < 2; ks++) {
            const int k0 = ks * 8;
            uint32_t af[2][4];
            #pragma unroll
            for (int s = 0; s < 2; s++) {
                const int mb = mw * 32 + s * 16;
                af[s][0] = At[(mb + gr) * 260 + n0 + k0 + ctg];
                af[s][1] = At[(mb + gr + 8) * 260 + n0 + k0 + ctg];
                af[s][2] = At[(mb + gr) * 260 + n0 + k0 + ctg + 4];
                af[s][3] = At[(mb + gr + 8) * 260 + n0 + k0 + ctg + 4];
                rna4(af[s]);
            }
            #pragma unroll
            for (int jp = 0; jp < 8; jp++) {
                const int v0 = nh * 64 + jp * 8;
                uint32_t b0 = rna(Vt[(k0 + ctg) * 264 + v0 + gr]);
                uint32_t b1 = rna(Vt[(k0 + ctg + 4) * 264 + v0 + gr]);
                mma1688(acc[0][jp], af[0], b0, b1);
                mma1688(acc[1][jp], af[1], b0, b1);
            }
        }
    };

    ISSUE2(0); ISSUE2(1);
    #pragma unroll
    for (int s = 0; s < 2; s++)
        #pragma unroll
        for (int j = 0; j < 8; j++)
            #pragma unroll
            for (int c = 0; c < 4; c++) acc[s][j][c] = 0.f;

    for (int ch = 0; ch < 15; ch++) {            // 15*16 = 240 >= 225
        if (ch < 13) { CP_WAIT1(); } else { CP_WAIT0(); }
        __syncthreads();                         // also orders PT stores (ch==0)
        MMA2(ch);
        if (ch + 2 < 15) ISSUE2(ch + 2);
    }

    float* obase = out + (size_t)b * OUTC * MH;
    #pragma unroll
    for (int s = 0; s < 2; s++)
        #pragma unroll
        for (int h = 0; h < 2; h++) {
            int gm = m0 + mw * 32 + s * 16 + lr + h * 8;
            if (gm >= MH) continue;
            #pragma unroll
            for (int j = 0; j < 8; j++) {
                int v0 = nh * 64 + j * 8 + 2 * l4;
                obase[(size_t)v0 * MH + gm]       = acc[s][j][2*h];
                obase[(size_t)(v0 + 1) * MH + gm] = acc[s][j][2*h+1];
            }
        }

    // =========== fused concat copy: out[b][256+c][m-tile] = q_out ==========
    {
        const int mloc = tid & 63, cb = tid >> 6;     // 4 channels per pass
        const int gm = m0 + mloc;
        if (gm < MH) {
            const float* qb = q_out + (size_t)b * 256 * MH + gm;
            float* ob = out + (size_t)b * OUTC * MH + (size_t)256 * MH + gm;
            #pragma unroll 4
            for (int c = cb; c < 256; c += 4)
                ob[(size_t)c * MH] = qb[(size_t)c * MH];
        }
    }
}

// ---------------------------------------------------------------------------
extern "C" void kernel_launch(void* const* d_in, const int* in_sizes, int n_in,
                              void* d_out, int out_size)
{
    const float* m_in  = (const float*)d_in[0];
    const float* m_out = (const float*)d_in[1];
    const float* q_in  = (const float*)d_in[2];
    const float* q_out = (const float*)d_in[3];
    float* out = (float*)d_out;
    float* p   = out + (size_t)B_ * OUTC * MH;

    cudaFuncSetAttribute(k_fused, cudaFuncAttributeMaxDynamicSharedMemorySize, SM_F);

    k_fused<<<dim3(4, B_), 256, SM_F>>>(q_in, m_in, m_out, q_out, p, out);
}

// round 13
// speedup vs baseline: 1.0791x; 1.0791x over previous
#include <cuda_runtime.h>
#include <cuda_bf16.h>
#include <cstdint>

#define B_   512
#define NC   225
#define CK   256
#define MH   225
#define VD   256
#define OUTC 512

// ---------------- helpers ----------------
__device__ __forceinline__ uint32_t smem_u32(const void* p) {
    uint32_t a;
    asm("{ .reg .u64 t; cvta.to.shared.u64 t, %1; cvt.u32.u64 %0, t; }" : "=r"(a) : "l"(p));
    return a;
}
__device__ __forceinline__ void ldm4(uint32_t* r, uint32_t addr) {
    asm volatile("ldmatrix.sync.aligned.m8n8.x4.shared.b16 {%0,%1,%2,%3}, [%4];"
                 : "=r"(r[0]), "=r"(r[1]), "=r"(r[2]), "=r"(r[3]) : "r"(addr));
}
__device__ __forceinline__ uint32_t rna(uint32_t u) {
    uint32_t r;
    asm("cvt.rna.tf32.f32 %0, %1;" : "=r"(r) : "f"(__uint_as_float(u)));
    return r;
}
__device__ __forceinline__ void rna4(uint32_t* r) {
    r[0] = rna(r[0]); r[1] = rna(r[1]); r[2] = rna(r[2]); r[3] = rna(r[3]);
}
__device__ __forceinline__ void mma1688(float* d, const uint32_t* a, uint32_t b0, uint32_t b1) {
    asm volatile("mma.sync.aligned.m16n8k8.row.col.f32.tf32.tf32.f32 "
                 "{%0,%1,%2,%3}, {%4,%5,%6,%7}, {%8,%9}, {%0,%1,%2,%3};"
                 : "+f"(d[0]), "+f"(d[1]), "+f"(d[2]), "+f"(d[3])
                 : "r"(a[0]), "r"(a[1]), "r"(a[2]), "r"(a[3]), "r"(b0), "r"(b1));
}
__device__ __forceinline__ void cpa4(uint32_t d, const float* s, int sz) {
    asm volatile("cp.async.ca.shared.global [%0], [%1], 4, %2;" :: "r"(d), "l"(s), "r"(sz));
}
__device__ __forceinline__ void cpa16(uint32_t d, const float* s, int sz) {
    asm volatile("cp.async.cg.shared.global [%0], [%1], 16, %2;" :: "r"(d), "l"(s), "r"(sz));
}
#define CP_COMMIT() asm volatile("cp.async.commit_group;" ::: "memory")
#define CP_WAIT2()  asm volatile("cp.async.wait_group 2;" ::: "memory")
#define CP_WAIT1()  asm volatile("cp.async.wait_group 1;" ::: "memory")
#define CP_WAIT0()  asm volatile("cp.async.wait_group 0;" ::: "memory")
__device__ __forceinline__ int iabs(int x) { return x < 0 ? -x : x; }

// ---- phase-1 smem: 4 buffers, per buffer A 64x80 | B 256x80 ----
#define BUFB   5120
#define BUFSZ  25600
// ---- phase-2 smem (reuses phase-1 buffer space) ----
#define PT_O   0              // p tile f32 [64m][260w] = 66560 B (A operand)
#define B2_O   66560          // 2 x m_out chunk [16n][264w] = 16896 B each
#define OT_O   0              // out tile f32 [256v][68w] = 69632 B (after MMA2)
// ---- persistent ----
#define PW_O   102400
#define RMX_O  102560
#define RS_O   103584
#define SM_F   104608

// ========================= fused GEMM1+softmax+GEMM2 =======================
__global__ __launch_bounds__(256, 2)
void k_fused(const float* __restrict__ q_in, const float* __restrict__ m_in,
             const float* __restrict__ m_out,
             float* __restrict__ p_out, float* __restrict__ out)
{
    extern __shared__ char sm[];
    const uint32_t su = smem_u32(sm);
    const int tid = threadIdx.x, lane = tid & 31, w = tid >> 5;
    const int mw = w & 1, nh = w >> 1;
    const int b = blockIdx.y, m0 = blockIdx.x * 64;

    float* PWS = (float*)(sm + PW_O);
    float* RMX = (float*)(sm + RMX_O);
    float* RS  = (float*)(sm + RS_O);
    if (tid < 32) {
        float v = 0.0625f;               // fold 1/sqrt(256)
        for (int i = 0; i < tid; i++) v *= 0.92f;
        PWS[tid] = v;
    }

    const float* Aq = q_in + (size_t)b * CK * MH;    // [c][m]
    const float* Bm = m_in + (size_t)b * NC * CK;    // [n][c]
    const float* Bo = m_out + (size_t)b * NC * VD;   // [n][v]

    float acc[2][8][4];
    #pragma unroll
    for (int s = 0; s < 2; s++)
        #pragma unroll
        for (int j = 0; j < 8; j++)
            #pragma unroll
            for (int c = 0; c < 4; c++) acc[s][j][c] = 0.f;

    // ---- phase-1 ldmatrix addresses ----
    const int row_a = (lane & 7) + ((lane >> 3) & 1) * 8;
    const int koff_a = (lane >> 4) * 16;
    const int nloc_b = (lane & 7) + ((lane >> 4) & 1) * 8;
    const int koff_b = ((lane >> 3) & 1) * 16;
    uint32_t a_ad[2], b_ad[4];
    #pragma unroll
    for (int s = 0; s < 2; s++)
        a_ad[s] = su + (uint32_t)((mw * 32 + s * 16 + row_a) * 80 + koff_a);
    #pragma unroll
    for (int jp = 0; jp < 4; jp++)
        b_ad[jp] = su + BUFB + (uint32_t)((nh * 64 + jp * 16 + nloc_b) * 80 + koff_b);

    // phase-1 copy maps
    const int amm = tid & 63, acb = (tid >> 6) * 4;
    const int agm = m0 + amm;
    const int agmc = (agm < MH) ? agm : 0;
    const int asz = (agm < MH) ? 4 : 0;
    const int bnn = tid;
    const int bnnc = (bnn < NC) ? bnn : 0;
    const int bsz = (bnn < NC) ? 16 : 0;

    auto ISSUE1 = [&](int ch) {
        const int c0 = ch * 16;
        const uint32_t bo = su + (uint32_t)((ch & 3) * BUFSZ);
        #pragma unroll
        for (int t = 0; t < 4; t++)
            cpa4(bo + amm * 80 + (acb + t) * 4,
                 Aq + (size_t)(c0 + acb + t) * MH + agmc, asz);
        #pragma unroll
        for (int q = 0; q < 4; q++)
            cpa16(bo + BUFB + bnn * 80 + q * 16,
                  Bm + (size_t)bnnc * CK + c0 + q * 4, bsz);
        CP_COMMIT();
    };
    auto MMA1 = [&](uint32_t bo) {
        #pragma unroll
        for (int ks = 0; ks < 2; ks++) {
            uint32_t a0[4], a1[4];
            ldm4(a0, a_ad[0] + bo + ks * 32);
            ldm4(a1, a_ad[1] + bo + ks * 32);
            rna4(a0); rna4(a1);
            #pragma unroll
            for (int jp = 0; jp < 4; jp++) {
                uint32_t bf[4];
                ldm4(bf, b_ad[jp] + bo + ks * 32);
                rna4(bf);
                mma1688(acc[0][2*jp],   a0, bf[0], bf[1]);
                mma1688(acc[0][2*jp+1], a0, bf[2], bf[3]);
                mma1688(acc[1][2*jp],   a1, bf[0], bf[1]);
                mma1688(acc[1][2*jp+1], a1, bf[2], bf[3]);
            }
        }
    };

    // phase-2 B copy map (used by ISSUE2, declared early for prefetch)
    const int bnl = tid >> 4, bvq = tid & 15;
    auto ISSUE2 = [&](int ch) {
        const int n0 = ch * 16;
        const uint32_t bo = su + (uint32_t)(B2_O + (ch & 1) * 16896);
        const int sz = (n0 + bnl < NC) ? 16 : 0;
        const float* brow = Bo + (size_t)((n0 + bnl < NC) ? (n0 + bnl) : 0) * VD + bvq * 16;
        #pragma unroll
        for (int i = 0; i < 4; i++)
            cpa16(bo + bnl * 1056 + bvq * 64 + i * 16, brow + i * 4, sz);
        CP_COMMIT();
    };

    ISSUE1(0); ISSUE1(1); ISSUE1(2);
    for (int ch = 0; ch < 16; ch++) {
        if (ch < 13) { CP_WAIT2(); } else { CP_WAIT0(); }
        __syncthreads();
        MMA1((uint32_t)((ch & 3) * BUFSZ));
        if (ch + 3 < 16) ISSUE1(ch + 3);
    }

    // ---------------- fused masked softmax over n ----------------
    const int l4 = lane & 3, lr = lane >> 2;
    int rl[2][2], xm[2][2], ym[2][2];
    #pragma unroll
    for (int s = 0; s < 2; s++)
        #pragma unroll
        for (int h = 0; h < 2; h++) {
            rl[s][h] = mw * 32 + s * 16 + lr + h * 8;
            int gm = m0 + rl[s][h];
            int gmc = (gm < MH) ? gm : MH - 1;
            xm[s][h] = gmc / 15; ym[s][h] = gmc - 15 * xm[s][h];
        }

    float mx[2][2] = {{-1e30f, -1e30f}, {-1e30f, -1e30f}};
    #pragma unroll
    for (int s = 0; s < 2; s++)
        #pragma unroll
        for (int j = 0; j < 8; j++)
            #pragma unroll
            for (int h = 0; h < 2; h++)
                #pragma unroll
                for (int c = 0; c < 2; c++) {
                    int n = nh * 64 + j * 8 + 2 * l4 + c;
                    int xn = n / 15, yn = n - 15 * xn;
                    float v = (n < NC)
                        ? acc[s][j][2*h+c] * PWS[iabs(xn - xm[s][h]) + iabs(yn - ym[s][h])]
                        : -1e30f;
                    acc[s][j][2*h+c] = v;
                    mx[s][h] = fmaxf(mx[s][h], v);
                }
    #pragma unroll
    for (int s = 0; s < 2; s++)
        #pragma unroll
        for (int h = 0; h < 2; h++) {
            mx[s][h] = fmaxf(mx[s][h], __shfl_xor_sync(~0u, mx[s][h], 1));
            mx[s][h] = fmaxf(mx[s][h], __shfl_xor_sync(~0u, mx[s][h], 2));
            if (l4 == 0) RMX[nh * 64 + rl[s][h]] = mx[s][h];
        }
    __syncthreads();           // all phase-1 buffer reads complete here

    // early prefetch of first two m_out chunks — overlaps softmax + p copy
    ISSUE2(0); ISSUE2(1);

    #pragma unroll
    for (int s = 0; s < 2; s++)
        #pragma unroll
        for (int h = 0; h < 2; h++) {
            float m1 = fmaxf(RMX[rl[s][h]], RMX[64 + rl[s][h]]);
            float m2 = fmaxf(RMX[128 + rl[s][h]], RMX[192 + rl[s][h]]);
            mx[s][h] = fmaxf(m1, m2);
        }
    float sum[2][2] = {{0.f, 0.f}, {0.f, 0.f}};
    #pragma unroll
    for (int s = 0; s < 2; s++)
        #pragma unroll
        for (int j = 0; j < 8; j++)
            #pragma unroll
            for (int h = 0; h < 2; h++) {
                sum[s][h] += __expf(acc[s][j][2*h]   - mx[s][h]);
                sum[s][h] += __expf(acc[s][j][2*h+1] - mx[s][h]);
            }
    __syncthreads();
    #pragma unroll
    for (int s = 0; s < 2; s++)
        #pragma unroll
        for (int h = 0; h < 2; h++) {
            sum[s][h] += __shfl_xor_sync(~0u, sum[s][h], 1);
            sum[s][h] += __shfl_xor_sync(~0u, sum[s][h], 2);
            if (l4 == 0) RS[nh * 64 + rl[s][h]] = sum[s][h];
        }
    __syncthreads();
    float inv[2][2];
    #pragma unroll
    for (int s = 0; s < 2; s++)
        #pragma unroll
        for (int h = 0; h < 2; h++)
            inv[s][h] = 1.0f / (RS[rl[s][h]] + RS[64 + rl[s][h]]
                              + RS[128 + rl[s][h]] + RS[192 + rl[s][h]]);

    // write p tile to smem only (pitch 260 words, zero-padded n>=225)
    float* PT = (float*)(sm + PT_O);
    #pragma unroll
    for (int s = 0; s < 2; s++)
        #pragma unroll
        for (int h = 0; h < 2; h++) {
            float* prow = PT + rl[s][h] * 260;
            #pragma unroll
            for (int j = 0; j < 8; j++) {
                int n0 = nh * 64 + j * 8 + 2 * l4;
                float p0 = __expf(acc[s][j][2*h]   - mx[s][h]) * inv[s][h];
                float p1 = __expf(acc[s][j][2*h+1] - mx[s][h]) * inv[s][h];
                float z0 = (n0 < NC) ? p0 : 0.0f;
                float z1 = (n0 + 1 < NC) ? p1 : 0.0f;
                *(float2*)(prow + n0) = make_float2(z0, z1);
            }
        }
    __syncthreads();

    // coalesced p output: warp covers consecutive m at fixed n
    {
        float* pbase = p_out + (size_t)b * NC * MH;
        for (int i = tid; i < NC * 64; i += 256) {
            int n = i >> 6, mloc = i & 63;
            int gm = m0 + mloc;
            if (gm < MH) pbase[(size_t)n * MH + gm] = PT[mloc * 260 + n];
        }
    }

    // =================== phase 2: D[m,v] = p * m_out ===================
    const int gr = lane >> 2, ctg = lane & 3;
    auto MMA2 = [&](int ch) {
        const int n0 = ch * 16;
        const uint32_t* At = (const uint32_t*)(sm + PT_O);                       // [64][260]
        const uint32_t* Vt = (const uint32_t*)(sm + B2_O + (ch & 1) * 16896);    // [16][264]
        #pragma unroll
        for (int ks = 0; ks < 2; ks++) {
            const int k0 = ks * 8;
            uint32_t af[2][4];
            #pragma unroll
            for (int s = 0; s < 2; s++) {
                const int mb = mw * 32 + s * 16;
                af[s][0] = At[(mb + gr) * 260 + n0 + k0 + ctg];
                af[s][1] = At[(mb + gr + 8) * 260 + n0 + k0 + ctg];
                af[s][2] = At[(mb + gr) * 260 + n0 + k0 + ctg + 4];
                af[s][3] = At[(mb + gr + 8) * 260 + n0 + k0 + ctg + 4];
                rna4(af[s]);
            }
            #pragma unroll
            for (int jp = 0; jp < 8; jp++) {
                const int v0 = nh * 64 + jp * 8;
                uint32_t b0 = rna(Vt[(k0 + ctg) * 264 + v0 + gr]);
                uint32_t b1 = rna(Vt[(k0 + ctg + 4) * 264 + v0 + gr]);
                mma1688(acc[0][jp], af[0], b0, b1);
                mma1688(acc[1][jp], af[1], b0, b1);
            }
        }
    };

    #pragma unroll
    for (int s = 0; s < 2; s++)
        #pragma unroll
        for (int j = 0; j < 8; j++)
            #pragma unroll
            for (int c = 0; c < 4; c++) acc[s][j][c] = 0.f;

    for (int ch = 0; ch < 15; ch++) {            // 15*16 = 240 >= 225
        if (ch < 13) { CP_WAIT1(); } else { CP_WAIT0(); }
        __syncthreads();
        MMA2(ch);
        if (ch + 2 < 15) ISSUE2(ch + 2);
    }
    __syncthreads();                             // all PT/B2 reads done

    // stage out fragments in smem (pitch 68: conflict-free writes)
    float* OT = (float*)(sm + OT_O);
    #pragma unroll
    for (int s = 0; s < 2; s++)
        #pragma unroll
        for (int h = 0; h < 2; h++) {
            int row = rl[s][h];
            #pragma unroll
            for (int j = 0; j < 8; j++) {
                int v0 = nh * 64 + j * 8 + 2 * l4;
                OT[(v0)     * 68 + row] = acc[s][j][2*h];
                OT[(v0 + 1) * 68 + row] = acc[s][j][2*h+1];
            }
        }
    __syncthreads();

    // coalesced mem_out: warp covers consecutive m at fixed v
    {
        float* obase = out + (size_t)b * OUTC * MH;
        for (int i = tid; i < 256 * 64; i += 256) {
            int v = i >> 6, mloc = i & 63;
            int gm = m0 + mloc;
            if (gm < MH) obase[(size_t)v * MH + gm] = OT[v * 68 + mloc];
        }
    }
}

// ============================ concat copy ==================================
__global__ __launch_bounds__(256) void k_copy(const float4* __restrict__ q,
                                              float* __restrict__ out)
{
    const int TOT4 = (B_ * 256 * MH) / 4;
    int i = blockIdx.x * blockDim.x + threadIdx.x;
    if (i >= TOT4) return;
    int b = i / 14400;
    float4 v = q[i];
    *(float4*)(out + (size_t)(b + 1) * 57600 + (size_t)i * 4) = v;
}

// ---------------------------------------------------------------------------
extern "C" void kernel_launch(void* const* d_in, const int* in_sizes, int n_in,
                              void* d_out, int out_size)
{
    const float* m_in  = (const float*)d_in[0];
    const float* m_out = (const float*)d_in[1];
    const float* q_in  = (const float*)d_in[2];
    const float* q_out = (const float*)d_in[3];
    float* out = (float*)d_out;
    float* p   = out + (size_t)B_ * OUTC * MH;

    cudaFuncSetAttribute(k_fused, cudaFuncAttributeMaxDynamicSharedMemorySize, SM_F);

    k_fused<<<dim3(4, B_), 256, SM_F>>>(q_in, m_in, m_out, p, out);
    const int TOT4 = (B_ * 256 * MH) / 4;
    k_copy<<<(TOT4 + 255) / 256, 256>>>((const float4*)q_out, out);
}

// round 14
// speedup vs baseline: 1.1182x; 1.0362x over previous
#include <cuda_runtime.h>
#include <cuda_bf16.h>
#include <cstdint>

#define B_   512
#define NC   225
#define CK   256
#define MH   225
#define VD   256
#define OUTC 512

// ---------------- helpers ----------------
__device__ __forceinline__ uint32_t smem_u32(const void* p) {
    uint32_t a;
    asm("{ .reg .u64 t; cvta.to.shared.u64 t, %1; cvt.u32.u64 %0, t; }" : "=r"(a) : "l"(p));
    return a;
}
__device__ __forceinline__ void ldm4(uint32_t* r, uint32_t addr) {
    asm volatile("ldmatrix.sync.aligned.m8n8.x4.shared.b16 {%0,%1,%2,%3}, [%4];"
                 : "=r"(r[0]), "=r"(r[1]), "=r"(r[2]), "=r"(r[3]) : "r"(addr));
}
__device__ __forceinline__ uint32_t rna(uint32_t u) {
    uint32_t r;
    asm("cvt.rna.tf32.f32 %0, %1;" : "=r"(r) : "f"(__uint_as_float(u)));
    return r;
}
__device__ __forceinline__ void rna4(uint32_t* r) {
    r[0] = rna(r[0]); r[1] = rna(r[1]); r[2] = rna(r[2]); r[3] = rna(r[3]);
}
__device__ __forceinline__ void mma1688(float* d, const uint32_t* a, uint32_t b0, uint32_t b1) {
    asm volatile("mma.sync.aligned.m16n8k8.row.col.f32.tf32.tf32.f32 "
                 "{%0,%1,%2,%3}, {%4,%5,%6,%7}, {%8,%9}, {%0,%1,%2,%3};"
                 : "+f"(d[0]), "+f"(d[1]), "+f"(d[2]), "+f"(d[3])
                 : "r"(a[0]), "r"(a[1]), "r"(a[2]), "r"(a[3]), "r"(b0), "r"(b1));
}
__device__ __forceinline__ void cpa4(uint32_t d, const float* s, int sz) {
    asm volatile("cp.async.ca.shared.global [%0], [%1], 4, %2;" :: "r"(d), "l"(s), "r"(sz));
}
__device__ __forceinline__ void cpa16(uint32_t d, const float* s, int sz) {
    asm volatile("cp.async.cg.shared.global [%0], [%1], 16, %2;" :: "r"(d), "l"(s), "r"(sz));
}
#define CP_COMMIT() asm volatile("cp.async.commit_group;" ::: "memory")
#define CP_WAIT2()  asm volatile("cp.async.wait_group 2;" ::: "memory")
#define CP_WAIT1()  asm volatile("cp.async.wait_group 1;" ::: "memory")
#define CP_WAIT0()  asm volatile("cp.async.wait_group 0;" ::: "memory")
__device__ __forceinline__ int iabs(int x) { return x < 0 ? -x : x; }

// ---- phase-1 smem: 4 buffers, per buffer A 64x80 | B 256x80 ----
#define BUFB   5120
#define BUFSZ  25600
// ---- phase-2 smem (reuses phase-1 buffer space) ----
#define PT_O   0              // p tile f32 [64m][260w] = 66560 B (A operand)
#define B2_O   66560          // 2 x m_out chunk [16n][264w] = 16896 B each
#define OT_O   0              // out tile f32 [256v][68w] = 69632 B (after MMA2)
// ---- persistent ----
#define PW_O   102400
#define RMX_O  102560
#define RS_O   103584
#define SM_F   104608

// ============== fused GEMM1+softmax+GEMM2 + interleaved copies =============
__global__ __launch_bounds__(256, 2)
void k_fused(const float* __restrict__ q_in, const float* __restrict__ m_in,
             const float* __restrict__ m_out, const float* __restrict__ q_out,
             float* __restrict__ p_out, float* __restrict__ out)
{
    extern __shared__ char sm[];
    const uint32_t su = smem_u32(sm);
    const int tid = threadIdx.x, lane = tid & 31, w = tid >> 5;
    const int mw = w & 1, nh = w >> 1;
    const int b = blockIdx.y, m0 = blockIdx.x * 64;

    float* PWS = (float*)(sm + PW_O);
    float* RMX = (float*)(sm + RMX_O);
    float* RS  = (float*)(sm + RS_O);
    if (tid < 32) {
        float v = 0.0625f;               // fold 1/sqrt(256)
        for (int i = 0; i < tid; i++) v *= 0.92f;
        PWS[tid] = v;
    }

    const float* Aq = q_in + (size_t)b * CK * MH;    // [c][m]
    const float* Bm = m_in + (size_t)b * NC * CK;    // [n][c]
    const float* Bo = m_out + (size_t)b * NC * VD;   // [n][v]

    // copy maps for interleaved q_out copy (phase 1) / p emit (phase 2)
    const int cml = tid & 63, ccg = tid >> 6;        // m-local, channel group
    const int cgm = m0 + cml;
    const float* qcb = q_out + (size_t)b * 256 * MH + ((cgm < MH) ? cgm : 0);
    float* ocb = out + (size_t)b * OUTC * MH + (size_t)256 * MH + ((cgm < MH) ? cgm : 0);
    float* pcb = p_out + (size_t)b * NC * MH + ((cgm < MH) ? cgm : 0);
    const bool cok = (cgm < MH);

    float acc[2][8][4];
    #pragma unroll
    for (int s = 0; s < 2; s++)
        #pragma unroll
        for (int j = 0; j < 8; j++)
            #pragma unroll
            for (int c = 0; c < 4; c++) acc[s][j][c] = 0.f;

    // ---- phase-1 ldmatrix addresses ----
    const int row_a = (lane & 7) + ((lane >> 3) & 1) * 8;
    const int koff_a = (lane >> 4) * 16;
    const int nloc_b = (lane & 7) + ((lane >> 4) & 1) * 8;
    const int koff_b = ((lane >> 3) & 1) * 16;
    uint32_t a_ad[2], b_ad[4];
    #pragma unroll
    for (int s = 0; s < 2; s++)
        a_ad[s] = su + (uint32_t)((mw * 32 + s * 16 + row_a) * 80 + koff_a);
    #pragma unroll
    for (int jp = 0; jp < 4; jp++)
        b_ad[jp] = su + BUFB + (uint32_t)((nh * 64 + jp * 16 + nloc_b) * 80 + koff_b);

    // phase-1 cp.async maps
    const int amm = tid & 63, acb = (tid >> 6) * 4;
    const int agm = m0 + amm;
    const int agmc = (agm < MH) ? agm : 0;
    const int asz = (agm < MH) ? 4 : 0;
    const int bnn = tid;
    const int bnnc = (bnn < NC) ? bnn : 0;
    const int bsz = (bnn < NC) ? 16 : 0;

    auto ISSUE1 = [&](int ch) {
        const int c0 = ch * 16;
        const uint32_t bo = su + (uint32_t)((ch & 3) * BUFSZ);
        #pragma unroll
        for (int t = 0; t < 4; t++)
            cpa4(bo + amm * 80 + (acb + t) * 4,
                 Aq + (size_t)(c0 + acb + t) * MH + agmc, asz);
        #pragma unroll
        for (int q = 0; q < 4; q++)
            cpa16(bo + BUFB + bnn * 80 + q * 16,
                  Bm + (size_t)bnnc * CK + c0 + q * 4, bsz);
        CP_COMMIT();
    };
    auto MMA1 = [&](uint32_t bo) {
        #pragma unroll
        for (int ks = 0; ks < 2; ks++) {
            uint32_t a0[4], a1[4];
            ldm4(a0, a_ad[0] + bo + ks * 32);
            ldm4(a1, a_ad[1] + bo + ks * 32);
            rna4(a0); rna4(a1);
            #pragma unroll
            for (int jp = 0; jp < 4; jp++) {
                uint32_t bf[4];
                ldm4(bf, b_ad[jp] + bo + ks * 32);
                rna4(bf);
                mma1688(acc[0][2*jp],   a0, bf[0], bf[1]);
                mma1688(acc[0][2*jp+1], a0, bf[2], bf[3]);
                mma1688(acc[1][2*jp],   a1, bf[0], bf[1]);
                mma1688(acc[1][2*jp+1], a1, bf[2], bf[3]);
            }
        }
    };

    // phase-2 B copy map (declared early for prefetch)
    const int bnl = tid >> 4, bvq = tid & 15;
    auto ISSUE2 = [&](int ch) {
        const int n0 = ch * 16;
        const uint32_t bo = su + (uint32_t)(B2_O + (ch & 1) * 16896);
        const int sz = (n0 + bnl < NC) ? 16 : 0;
        const float* brow = Bo + (size_t)((n0 + bnl < NC) ? (n0 + bnl) : 0) * VD + bvq * 16;
        #pragma unroll
        for (int i = 0; i < 4; i++)
            cpa16(bo + bnl * 1056 + bvq * 64 + i * 16, brow + i * 4, sz);
        CP_COMMIT();
    };

    // ============ phase-1 mainloop with interleaved q_out copy ============
    ISSUE1(0); ISSUE1(1); ISSUE1(2);
    for (int ch = 0; ch < 16; ch++) {
        // q_out copy loads: 4 channels (c = ch*16 + ccg*4 + t)
        float cv0, cv1, cv2, cv3;
        {
            const size_t cb0 = (size_t)(ch * 16 + ccg * 4) * MH;
            cv0 = qcb[cb0];
            cv1 = qcb[cb0 + MH];
            cv2 = qcb[cb0 + 2 * MH];
            cv3 = qcb[cb0 + 3 * MH];
        }
        if (ch < 13) { CP_WAIT2(); } else { CP_WAIT0(); }
        __syncthreads();
        MMA1((uint32_t)((ch & 3) * BUFSZ));
        if (ch + 3 < 16) ISSUE1(ch + 3);
        if (cok) {
            const size_t cb0 = (size_t)(ch * 16 + ccg * 4) * MH;
            ocb[cb0] = cv0;
            ocb[cb0 + MH] = cv1;
            ocb[cb0 + 2 * MH] = cv2;
            ocb[cb0 + 3 * MH] = cv3;
        }
    }

    // ---------------- fused masked softmax over n ----------------
    const int l4 = lane & 3, lr = lane >> 2;
    int rl[2][2], xm[2][2], ym[2][2];
    #pragma unroll
    for (int s = 0; s < 2; s++)
        #pragma unroll
        for (int h = 0; h < 2; h++) {
            rl[s][h] = mw * 32 + s * 16 + lr + h * 8;
            int gm = m0 + rl[s][h];
            int gmc = (gm < MH) ? gm : MH - 1;
            xm[s][h] = gmc / 15; ym[s][h] = gmc - 15 * xm[s][h];
        }

    float mx[2][2] = {{-1e30f, -1e30f}, {-1e30f, -1e30f}};
    #pragma unroll
    for (int s = 0; s < 2; s++)
        #pragma unroll
        for (int j = 0; j < 8; j++)
            #pragma unroll
            for (int h = 0; h < 2; h++)
                #pragma unroll
                for (int c = 0; c < 2; c++) {
                    int n = nh * 64 + j * 8 + 2 * l4 + c;
                    int xn = n / 15, yn = n - 15 * xn;
                    float v = (n < NC)
                        ? acc[s][j][2*h+c] * PWS[iabs(xn - xm[s][h]) + iabs(yn - ym[s][h])]
                        : -1e30f;
                    acc[s][j][2*h+c] = v;
                    mx[s][h] = fmaxf(mx[s][h], v);
                }
    #pragma unroll
    for (int s = 0; s < 2; s++)
        #pragma unroll
        for (int h = 0; h < 2; h++) {
            mx[s][h] = fmaxf(mx[s][h], __shfl_xor_sync(~0u, mx[s][h], 1));
            mx[s][h] = fmaxf(mx[s][h], __shfl_xor_sync(~0u, mx[s][h], 2));
            if (l4 == 0) RMX[nh * 64 + rl[s][h]] = mx[s][h];
        }
    __syncthreads();           // all phase-1 buffer reads complete here

    // early prefetch of first two m_out chunks — overlaps softmax
    ISSUE2(0); ISSUE2(1);

    #pragma unroll
    for (int s = 0; s < 2; s++)
        #pragma unroll
        for (int h = 0; h < 2; h++) {
            float m1 = fmaxf(RMX[rl[s][h]], RMX[64 + rl[s][h]]);
            float m2 = fmaxf(RMX[128 + rl[s][h]], RMX[192 + rl[s][h]]);
            mx[s][h] = fmaxf(m1, m2);
        }
    float sum[2][2] = {{0.f, 0.f}, {0.f, 0.f}};
    #pragma unroll
    for (int s = 0; s < 2; s++)
        #pragma unroll
        for (int j = 0; j < 8; j++)
            #pragma unroll
            for (int h = 0; h < 2; h++) {
                sum[s][h] += __expf(acc[s][j][2*h]   - mx[s][h]);
                sum[s][h] += __expf(acc[s][j][2*h+1] - mx[s][h]);
            }
    __syncthreads();
    #pragma unroll
    for (int s = 0; s < 2; s++)
        #pragma unroll
        for (int h = 0; h < 2; h++) {
            sum[s][h] += __shfl_xor_sync(~0u, sum[s][h], 1);
            sum[s][h] += __shfl_xor_sync(~0u, sum[s][h], 2);
            if (l4 == 0) RS[nh * 64 + rl[s][h]] = sum[s][h];
        }
    __syncthreads();
    float inv[2][2];
    #pragma unroll
    for (int s = 0; s < 2; s++)
        #pragma unroll
        for (int h = 0; h < 2; h++)
            inv[s][h] = 1.0f / (RS[rl[s][h]] + RS[64 + rl[s][h]]
                              + RS[128 + rl[s][h]] + RS[192 + rl[s][h]]);

    // write p tile to smem (pitch 260 words, zero-padded n>=225)
    float* PT = (float*)(sm + PT_O);
    #pragma unroll
    for (int s = 0; s < 2; s++)
        #pragma unroll
        for (int h = 0; h < 2; h++) {
            float* prow = PT + rl[s][h] * 260;
            #pragma unroll
            for (int j = 0; j < 8; j++) {
                int n0 = nh * 64 + j * 8 + 2 * l4;
                float p0 = __expf(acc[s][j][2*h]   - mx[s][h]) * inv[s][h];
                float p1 = __expf(acc[s][j][2*h+1] - mx[s][h]) * inv[s][h];
                float z0 = (n0 < NC) ? p0 : 0.0f;
                float z1 = (n0 + 1 < NC) ? p1 : 0.0f;
                *(float2*)(prow + n0) = make_float2(z0, z1);
            }
        }
    __syncthreads();

    // =========== phase 2: D[m,v] = p * m_out, interleaved p emit ===========
    const int gr = lane >> 2, ctg = lane & 3;
    auto MMA2 = [&](int ch) {
        const int n0 = ch * 16;
        const uint32_t* At = (const uint32_t*)(sm + PT_O);                       // [64][260]
        const uint32_t* Vt = (const uint32_t*)(sm + B2_O + (ch & 1) * 16896);    // [16][264]
        #pragma unroll
        for (int ks = 0; ks < 2; ks++) {
            const int k0 = ks * 8;
            uint32_t af[2][4];
            #pragma unroll
            for (int s = 0; s < 2; s++) {
                const int mb = mw * 32 + s * 16;
                af[s][0] = At[(mb + gr) * 260 + n0 + k0 + ctg];
                af[s][1] = At[(mb + gr + 8) * 260 + n0 + k0 + ctg];
                af[s][2] = At[(mb + gr) * 260 + n0 + k0 + ctg + 4];
                af[s][3] = At[(mb + gr + 8) * 260 + n0 + k0 + ctg + 4];
                rna4(af[s]);
            }
            #pragma unroll
            for (int jp = 0; jp < 8; jp++) {
                const int v0 = nh * 64 + jp * 8;
                uint32_t b0 = rna(Vt[(k0 + ctg) * 264 + v0 + gr]);
                uint32_t b1 = rna(Vt[(k0 + ctg + 4) * 264 + v0 + gr]);
                mma1688(acc[0][jp], af[0], b0, b1);
                mma1688(acc[1][jp], af[1], b0, b1);
            }
        }
    };

    #pragma unroll
    for (int s = 0; s < 2; s++)
        #pragma unroll
        for (int j = 0; j < 8; j++)
            #pragma unroll
            for (int c = 0; c < 4; c++) acc[s][j][c] = 0.f;

    for (int ch = 0; ch < 15; ch++) {            // 15*16 = 240 >= 225
        if (ch < 13) { CP_WAIT1(); } else { CP_WAIT0(); }
        __syncthreads();
        MMA2(ch);
        if (ch + 2 < 15) ISSUE2(ch + 2);
        // interleaved p emit: 4 n's (n = ch*16 + ccg*4 + t), coalesced 64-wide
        if (cok) {
            #pragma unroll
            for (int t = 0; t < 4; t++) {
                int n = ch * 16 + ccg * 4 + t;
                if (n < NC) pcb[(size_t)n * MH] = PT[cml * 260 + n];
            }
        }
    }
    __syncthreads();                             // all PT/B2 reads done

    // stage out fragments in smem (pitch 68: conflict-free writes)
    float* OT = (float*)(sm + OT_O);
    #pragma unroll
    for (int s = 0; s < 2; s++)
        #pragma unroll
        for (int h = 0; h < 2; h++) {
            int row = rl[s][h];
            #pragma unroll
            for (int j = 0; j < 8; j++) {
                int v0 = nh * 64 + j * 8 + 2 * l4;
                OT[(v0)     * 68 + row] = acc[s][j][2*h];
                OT[(v0 + 1) * 68 + row] = acc[s][j][2*h+1];
            }
        }
    __syncthreads();

    // coalesced mem_out: warp covers consecutive m at fixed v
    {
        float* obase = out + (size_t)b * OUTC * MH;
        for (int i = tid; i < 256 * 64; i += 256) {
            int v = i >> 6, mloc = i & 63;
            int gm = m0 + mloc;
            if (gm < MH) obase[(size_t)v * MH + gm] = OT[v * 68 + mloc];
        }
    }
}

// ---------------------------------------------------------------------------
extern "C" void kernel_launch(void* const* d_in, const int* in_sizes, int n_in,
                              void* d_out, int out_size)
{
    const float* m_in  = (const float*)d_in[0];
    const float* m_out = (const float*)d_in[1];
    const float* q_in  = (const float*)d_in[2];
    const float* q_out = (const float*)d_in[3];
    float* out = (float*)d_out;
    float* p   = out + (size_t)B_ * OUTC * MH;

    cudaFuncSetAttribute(k_fused, cudaFuncAttributeMaxDynamicSharedMemorySize, SM_F);

    k_fused<<<dim3(4, B_), 256, SM_F>>>(q_in, m_in, m_out, q_out, p, out);
}